// round 9
// baseline (speedup 1.0000x reference)
#include <cuda_runtime.h>
#include <cuda_fp16.h>
#include <cstdint>

#define F_SPARSE 26
#define BATCH    4096
#define ATT      64
#define NPAIR    325
#define M_TOTAL  (F_SPARSE * BATCH)   // 106496

// fp32 scratch: X[m][128], m = f*BATCH + b. 54.5 MB.
__device__ float g_X[(size_t)M_TOTAL * 128];

// ======================= common helpers ====================================
__device__ __forceinline__ uint32_t cvta_s(const void* p) {
    return (uint32_t)__cvta_generic_to_shared(p);
}
__device__ __forceinline__ void ldsm_x4(uint32_t a[4], uint32_t addr) {
    asm volatile("ldmatrix.sync.aligned.m8n8.x4.shared.b16 {%0,%1,%2,%3}, [%4];"
                 : "=r"(a[0]), "=r"(a[1]), "=r"(a[2]), "=r"(a[3]) : "r"(addr));
}
__device__ __forceinline__ void ldsm_x2(uint32_t b[2], uint32_t addr) {
    asm volatile("ldmatrix.sync.aligned.m8n8.x2.shared.b16 {%0,%1}, [%2];"
                 : "=r"(b[0]), "=r"(b[1]) : "r"(addr));
}
__device__ __forceinline__ void mma_f16(float c[4], const uint32_t a[4], const uint32_t b[2]) {
    asm volatile("mma.sync.aligned.m16n8k16.row.col.f32.f16.f16.f32 "
                 "{%0,%1,%2,%3}, {%4,%5,%6,%7}, {%8,%9}, {%0,%1,%2,%3};"
                 : "+f"(c[0]), "+f"(c[1]), "+f"(c[2]), "+f"(c[3])
                 : "r"(a[0]), "r"(a[1]), "r"(a[2]), "r"(a[3]), "r"(b[0]), "r"(b[1]));
}
__device__ __forceinline__ uint32_t pack_h2(float x, float y) {
    __half2 t; t.x = __float2half(x); t.y = __float2half(y);
    return *reinterpret_cast<uint32_t*>(&t);
}

// ======================= Kernel 1: X = E @ W1c (+b1) =======================
// fp16 2-term split: X = A_hi@B + A_lo@B, B fp16 single (err ~2^-11/sqrt3).
// CTA = 128 M-rows, N=128, K=128. 8 warps of m32n64. 2 CTAs/SM.
#define K1_MT      128
#define K1_THREADS 256
#define ROWB       272                 // 128 fp16 + 8 pad, bytes
#define SA_HI      0
#define SA_SZ      (K1_MT * ROWB)      // 34816
#define SA_LO      (SA_HI + SA_SZ)
#define SB_OFF     (SA_LO + SA_SZ)     // 69632
#define SB_SZ      (128 * ROWB)        // 34816
#define SVEC       (SB_OFF + SB_SZ)    // 104448 : b1 (64 f32)
#define K1_SMEM    (SVEC + 256)        // 104704  -> 2 CTAs/SM

__global__ void __launch_bounds__(K1_THREADS, 2)
k1_gemm(const float* __restrict__ emb, const float* __restrict__ W1,
        const float* __restrict__ b1)
{
    extern __shared__ char smem[];
    const int tid  = threadIdx.x;
    const int lane = tid & 31;
    const int warp = tid >> 5;
    const int m0   = blockIdx.x * K1_MT;

    // ---- A fill: 128 contiguous rows of emb -> fp16 hi/lo ----------------
    for (int idx = tid; idx < K1_MT * 32; idx += K1_THREADS) {
        const int r = idx >> 5;
        const int c = idx & 31;                       // k = 4c
        const float4 v = reinterpret_cast<const float4*>(emb)[(size_t)(m0 + r) * 32 + c];
        float vv[4] = {v.x, v.y, v.z, v.w};
        float hv[4];
        #pragma unroll
        for (int q = 0; q < 4; ++q)
            hv[q] = __half2float(__float2half(vv[q]));
        *reinterpret_cast<uint2*>(smem + SA_HI + r * ROWB + c * 8) =
            make_uint2(pack_h2(vv[0], vv[1]), pack_h2(vv[2], vv[3]));
        *reinterpret_cast<uint2*>(smem + SA_LO + r * ROWB + c * 8) =
            make_uint2(pack_h2(vv[0]-hv[0], vv[1]-hv[1]), pack_h2(vv[2]-hv[2], vv[3]-hv[3]));
    }
    // ---- B fill: W1c stored [n][k], fp16 single ---------------------------
    // n<64 -> W1[k][n] ; n>=64 -> W1[128+k][n-64]
    for (int idx = tid; idx < 128 * 32; idx += K1_THREADS) {
        const int n = idx >> 5;
        const int c = idx & 31;
        const int k = c * 4;
        const int rs = (n < 64) ? k : (128 + k);
        const int cs = n & 63;
        float vv[4];
        #pragma unroll
        for (int q = 0; q < 4; ++q)
            vv[q] = W1[(size_t)(rs + q) * ATT + cs];
        *reinterpret_cast<uint2*>(smem + SB_OFF + n * ROWB + k * 2) =
            make_uint2(pack_h2(vv[0], vv[1]), pack_h2(vv[2], vv[3]));
    }
    if (tid < 64)
        reinterpret_cast<float*>(smem + SVEC)[tid] = b1[tid];
    __syncthreads();

    // ---- MMA: 8 warps = 4 m32-subtiles x 2 n64-halves, 2 terms ------------
    const int msub32 = warp >> 1;          // 0..3
    const int nhalf  = warp & 1;
    const int mW     = msub32 * 32;
    const int n0     = nhalf * 64;

    float acc[2][8][4];
    #pragma unroll
    for (int ms = 0; ms < 2; ++ms)
        #pragma unroll
        for (int nt = 0; nt < 8; ++nt) {
            acc[ms][nt][0]=0.f; acc[ms][nt][1]=0.f; acc[ms][nt][2]=0.f; acc[ms][nt][3]=0.f;
        }

    const int midx = lane >> 3;
    const uint32_t aOff = (uint32_t)((mW + ((midx & 1) << 3) + (lane & 7)) * ROWB
                                     + ((midx >> 1) << 4));
    const uint32_t bOff = (uint32_t)((n0 + (lane & 7)) * ROWB + (((lane >> 3) & 1) << 4));
    const uint32_t saHi = cvta_s(smem + SA_HI);
    const uint32_t saLo = cvta_s(smem + SA_LO);
    const uint32_t sbB  = cvta_s(smem + SB_OFF);

    #pragma unroll
    for (int term = 0; term < 2; ++term) {   // hi@B, lo@B
        const uint32_t aBase = (term == 0) ? saHi : saLo;
        #pragma unroll
        for (int ks = 0; ks < 8; ++ks) {
            uint32_t bf[8][2];
            #pragma unroll
            for (int nt = 0; nt < 8; ++nt)
                ldsm_x2(bf[nt], sbB + bOff + ks * 32 + nt * (8 * ROWB));
            #pragma unroll
            for (int ms = 0; ms < 2; ++ms) {
                uint32_t a[4];
                ldsm_x4(a, aBase + aOff + ms * (16 * ROWB) + ks * 32);
                #pragma unroll
                for (int nt = 0; nt < 8; ++nt)
                    mma_f16(acc[ms][nt], a, bf[nt]);
            }
        }
    }

    // ---- Epilogue: add b1 (cols 0..63), direct float2 stores --------------
    const float* b1s = reinterpret_cast<const float*>(smem + SVEC);
    #pragma unroll
    for (int ms = 0; ms < 2; ++ms) {
        const int r0 = m0 + mW + ms * 16 + (lane >> 2);
        #pragma unroll
        for (int nt = 0; nt < 8; ++nt) {
            const int n = n0 + nt * 8 + (lane & 3) * 2;
            float ax = 0.f, ay = 0.f;
            if (nhalf == 0) { ax = b1s[n]; ay = b1s[n + 1]; }
            *reinterpret_cast<float2*>(&g_X[(size_t)r0 * 128 + n]) =
                make_float2(acc[ms][nt][0] + ax, acc[ms][nt][1] + ay);
            *reinterpret_cast<float2*>(&g_X[(size_t)(r0 + 8) * 128 + n]) =
                make_float2(acc[ms][nt][2] + ax, acc[ms][nt][3] + ay);
        }
    }
}

// ======================= Kernel 2: pairwise relu-dot =======================
// Thread computes a quad of outputs sharing Pa_i and W2 (group LUT).
#define K2_THREADS 256
#define K2_BT      4
#define XP2        132
#define XT_BYTES   (K2_BT * F_SPARSE * XP2 * 4)   // 54912
#define SW2_OFF    XT_BYTES
#define SLUT_OFF   (SW2_OFF + 256)                // 91 packed group entries
#define NGRP       91
#define K2_SMEM    (SLUT_OFF + NGRP * 4)          // 55532

__global__ void __launch_bounds__(K2_THREADS, 4)
k2_pairs(const float* __restrict__ W2, const float* __restrict__ b2,
         float* __restrict__ out)
{
    extern __shared__ char smem[];
    float* sX = reinterpret_cast<float*>(smem);
    const int tid   = threadIdx.x;
    const int bbase = blockIdx.x * K2_BT;

    // ---- X tile load: rows r = bl*26 + f ----------------------------------
    for (int idx = tid; idx < K2_BT * F_SPARSE * 32; idx += K2_THREADS) {
        const int r = idx >> 5;
        const int c = idx & 31;
        const int bl = r / F_SPARSE;
        const int f  = r - bl * F_SPARSE;
        const float4 v = reinterpret_cast<const float4*>(
            &g_X[(size_t)(f * BATCH + bbase + bl) * 128])[c];
        *reinterpret_cast<float4*>(sX + r * XP2 + c * 4) = v;
    }
    if (tid < 64)
        reinterpret_cast<float*>(smem + SW2_OFF)[tid] = W2[tid];
    // ---- group LUT: (i, j0, cnt<=4, pstart) packed in u32 -----------------
    if (tid < F_SPARSE - 1) {
        const int i = tid;
        int prefix = 0;
        for (int q = 0; q < i; ++q)
            prefix += (F_SPARSE - 1 - q + 3) >> 2;
        const int pbase = i * (F_SPARSE - 1) - (i * (i - 1)) / 2;
        const int numq  = (F_SPARSE - 1 - i + 3) >> 2;
        uint32_t* lut = reinterpret_cast<uint32_t*>(smem + SLUT_OFF);
        for (int q = 0; q < numq; ++q) {
            const int j0  = i + 1 + 4 * q;
            const int cnt = min(4, F_SPARSE - j0);
            const int ps  = pbase + (j0 - i - 1);
            lut[prefix + q] = (uint32_t)i | ((uint32_t)j0 << 5)
                            | ((uint32_t)cnt << 10) | ((uint32_t)ps << 16);
        }
    }
    const float b2v = b2[0];
    __syncthreads();

    const float4* sW24 = reinterpret_cast<const float4*>(smem + SW2_OFF);
    const uint32_t* lut = reinterpret_cast<const uint32_t*>(smem + SLUT_OFF);

    for (int g = tid; g < K2_BT * NGRP; g += K2_THREADS) {
        const int bl = g / NGRP;
        const int e  = g - bl * NGRP;
        const uint32_t ent = lut[e];
        const int i   = (int)(ent & 31u);
        const int j0  = (int)((ent >> 5) & 31u);
        const int cnt = (int)((ent >> 10) & 7u);
        const int ps  = (int)(ent >> 16);

        const float4* Pa = reinterpret_cast<const float4*>(sX + (bl * F_SPARSE + i) * XP2);
        const float4* Pb0 = reinterpret_cast<const float4*>(
            sX + (bl * F_SPARSE + min(j0 + 0, F_SPARSE - 1)) * XP2 + 64);
        const float4* Pb1 = reinterpret_cast<const float4*>(
            sX + (bl * F_SPARSE + min(j0 + 1, F_SPARSE - 1)) * XP2 + 64);
        const float4* Pb2 = reinterpret_cast<const float4*>(
            sX + (bl * F_SPARSE + min(j0 + 2, F_SPARSE - 1)) * XP2 + 64);
        const float4* Pb3 = reinterpret_cast<const float4*>(
            sX + (bl * F_SPARSE + min(j0 + 3, F_SPARSE - 1)) * XP2 + 64);

        float a0x = 0.f, a0y = 0.f, a1x = 0.f, a1y = 0.f;
        float a2x = 0.f, a2y = 0.f, a3x = 0.f, a3y = 0.f;
        #pragma unroll
        for (int t = 0; t < 16; ++t) {
            const float4 x = Pa[t];
            const float4 w = sW24[t];
            {
                const float4 y = Pb0[t];
                a0x = fmaf(fmaxf(x.x + y.x, 0.f), w.x, a0x);
                a0y = fmaf(fmaxf(x.y + y.y, 0.f), w.y, a0y);
                a0x = fmaf(fmaxf(x.z + y.z, 0.f), w.z, a0x);
                a0y = fmaf(fmaxf(x.w + y.w, 0.f), w.w, a0y);
            }
            {
                const float4 y = Pb1[t];
                a1x = fmaf(fmaxf(x.x + y.x, 0.f), w.x, a1x);
                a1y = fmaf(fmaxf(x.y + y.y, 0.f), w.y, a1y);
                a1x = fmaf(fmaxf(x.z + y.z, 0.f), w.z, a1x);
                a1y = fmaf(fmaxf(x.w + y.w, 0.f), w.w, a1y);
            }
            {
                const float4 y = Pb2[t];
                a2x = fmaf(fmaxf(x.x + y.x, 0.f), w.x, a2x);
                a2y = fmaf(fmaxf(x.y + y.y, 0.f), w.y, a2y);
                a2x = fmaf(fmaxf(x.z + y.z, 0.f), w.z, a2x);
                a2y = fmaf(fmaxf(x.w + y.w, 0.f), w.w, a2y);
            }
            {
                const float4 y = Pb3[t];
                a3x = fmaf(fmaxf(x.x + y.x, 0.f), w.x, a3x);
                a3y = fmaf(fmaxf(x.y + y.y, 0.f), w.y, a3y);
                a3x = fmaf(fmaxf(x.z + y.z, 0.f), w.z, a3x);
                a3y = fmaf(fmaxf(x.w + y.w, 0.f), w.w, a3y);
            }
        }
        float res[4] = {a0x + a0y, a1x + a1y, a2x + a2y, a3x + a3y};
        float* dst = out + (size_t)(bbase + bl) * NPAIR + ps;
        #pragma unroll
        for (int q = 0; q < 4; ++q)
            if (q < cnt) dst[q] = res[q] + b2v;
    }
}

// =========================== launcher ======================================
extern "C" void kernel_launch(void* const* d_in, const int* in_sizes, int n_in,
                              void* d_out, int out_size) {
    const float* emb = (const float*)d_in[0];
    const float* W1  = (const float*)d_in[1];
    const float* b1  = (const float*)d_in[2];
    const float* W2  = (const float*)d_in[3];
    const float* b2  = (const float*)d_in[4];
    float* out = (float*)d_out;
    (void)in_sizes; (void)n_in; (void)out_size;

    cudaFuncSetAttribute(k1_gemm,
                         cudaFuncAttributeMaxDynamicSharedMemorySize, K1_SMEM);
    cudaFuncSetAttribute(k2_pairs,
                         cudaFuncAttributeMaxDynamicSharedMemorySize, K2_SMEM);

    k1_gemm<<<M_TOTAL / K1_MT, K1_THREADS, K1_SMEM>>>(emb, W1, b1);
    k2_pairs<<<BATCH / K2_BT, K2_THREADS, K2_SMEM>>>(W2, b2, out);
}

// round 11
// speedup vs baseline: 1.4471x; 1.4471x over previous
#include <cuda_runtime.h>
#include <cuda_fp16.h>
#include <cstdint>

#define F_SPARSE 26
#define BATCH    4096
#define ATT      64
#define NPAIR    325
#define M_TOTAL  (F_SPARSE * BATCH)   // 106496

// fp32 scratch: X[m][128], m = f*BATCH + b. 54.5 MB.
__device__ float g_X[(size_t)M_TOTAL * 128];

// ======================= common helpers ====================================
__device__ __forceinline__ uint32_t cvta_s(const void* p) {
    return (uint32_t)__cvta_generic_to_shared(p);
}
__device__ __forceinline__ void ldsm_x4(uint32_t a[4], uint32_t addr) {
    asm volatile("ldmatrix.sync.aligned.m8n8.x4.shared.b16 {%0,%1,%2,%3}, [%4];"
                 : "=r"(a[0]), "=r"(a[1]), "=r"(a[2]), "=r"(a[3]) : "r"(addr));
}
__device__ __forceinline__ void ldsm_x2(uint32_t b[2], uint32_t addr) {
    asm volatile("ldmatrix.sync.aligned.m8n8.x2.shared.b16 {%0,%1}, [%2];"
                 : "=r"(b[0]), "=r"(b[1]) : "r"(addr));
}
__device__ __forceinline__ void mma_f16(float c[4], const uint32_t a[4], const uint32_t b[2]) {
    asm volatile("mma.sync.aligned.m16n8k16.row.col.f32.f16.f16.f32 "
                 "{%0,%1,%2,%3}, {%4,%5,%6,%7}, {%8,%9}, {%0,%1,%2,%3};"
                 : "+f"(c[0]), "+f"(c[1]), "+f"(c[2]), "+f"(c[3])
                 : "r"(a[0]), "r"(a[1]), "r"(a[2]), "r"(a[3]), "r"(b[0]), "r"(b[1]));
}
__device__ __forceinline__ uint32_t pack_h2(float x, float y) {
    __half2 t; t.x = __float2half(x); t.y = __float2half(y);
    return *reinterpret_cast<uint32_t*>(&t);
}

// ======================= Kernel 1: X = E @ W1c (+b1) =======================
// fp16 2-term split: X = A_hi@B + A_lo@B  (B fp16 single; validated 2.1e-4).
// CTA = 256 M-rows, 512 threads, 16 warps of m32n64.
#define K1_MT      256
#define K1_THREADS 512
#define ROWB       272                 // 128 fp16 + 8 pad, bytes
#define SA_HI      0
#define SA_SZ      (K1_MT * ROWB)      // 69632
#define SA_LO      (SA_HI + SA_SZ)
#define SB_OFF     (SA_LO + SA_SZ)     // 139264
#define SB_SZ      (128 * ROWB)        // 34816
#define SVEC       (SB_OFF + SB_SZ)    // 174080 : b1 (64 f32)
#define K1_SMEM    (SVEC + 256)        // 174336

__global__ void __launch_bounds__(K1_THREADS, 1)
k1_gemm(const float* __restrict__ emb, const float* __restrict__ W1,
        const float* __restrict__ b1)
{
    extern __shared__ char smem[];
    const int tid  = threadIdx.x;
    const int lane = tid & 31;
    const int warp = tid >> 5;
    const int m0   = blockIdx.x * K1_MT;

    // ---- A fill: 256 contiguous rows of emb -> fp16 hi/lo -----------------
    for (int idx = tid; idx < K1_MT * 32; idx += K1_THREADS) {
        const int r = idx >> 5;
        const int c = idx & 31;                       // k = 4c
        const float4 v = reinterpret_cast<const float4*>(emb)[(size_t)(m0 + r) * 32 + c];
        float vv[4] = {v.x, v.y, v.z, v.w};
        float hv[4];
        #pragma unroll
        for (int q = 0; q < 4; ++q)
            hv[q] = __half2float(__float2half(vv[q]));
        *reinterpret_cast<uint2*>(smem + SA_HI + r * ROWB + c * 8) =
            make_uint2(pack_h2(vv[0], vv[1]), pack_h2(vv[2], vv[3]));
        *reinterpret_cast<uint2*>(smem + SA_LO + r * ROWB + c * 8) =
            make_uint2(pack_h2(vv[0]-hv[0], vv[1]-hv[1]), pack_h2(vv[2]-hv[2], vv[3]-hv[3]));
    }
    // ---- B fill: W1c stored [n][k], fp16 single ---------------------------
    // n<64 -> W1[k][n] ; n>=64 -> W1[128+k][n-64]
    for (int idx = tid; idx < 128 * 32; idx += K1_THREADS) {
        const int n = idx >> 5;
        const int c = idx & 31;
        const int k = c * 4;
        const int rs = (n < 64) ? k : (128 + k);
        const int cs = n & 63;
        float vv[4];
        #pragma unroll
        for (int q = 0; q < 4; ++q)
            vv[q] = W1[(size_t)(rs + q) * ATT + cs];
        *reinterpret_cast<uint2*>(smem + SB_OFF + n * ROWB + k * 2) =
            make_uint2(pack_h2(vv[0], vv[1]), pack_h2(vv[2], vv[3]));
    }
    if (tid < 64)
        reinterpret_cast<float*>(smem + SVEC)[tid] = b1[tid];
    __syncthreads();

    // ---- MMA: 16 warps = 8 m32-subtiles x 2 n64-halves --------------------
    // B fragments hoisted: loaded once per k-step, reused by both A terms.
    const int msub32 = warp >> 1;          // 0..7
    const int nhalf  = warp & 1;
    const int mW     = msub32 * 32;
    const int n0     = nhalf * 64;

    float acc[2][8][4];
    #pragma unroll
    for (int ms = 0; ms < 2; ++ms)
        #pragma unroll
        for (int nt = 0; nt < 8; ++nt) {
            acc[ms][nt][0]=0.f; acc[ms][nt][1]=0.f; acc[ms][nt][2]=0.f; acc[ms][nt][3]=0.f;
        }

    const int midx = lane >> 3;
    const uint32_t aOff = (uint32_t)((mW + ((midx & 1) << 3) + (lane & 7)) * ROWB
                                     + ((midx >> 1) << 4));
    const uint32_t bOff = (uint32_t)((n0 + (lane & 7)) * ROWB + (((lane >> 3) & 1) << 4));
    const uint32_t saHi = cvta_s(smem + SA_HI);
    const uint32_t saLo = cvta_s(smem + SA_LO);
    const uint32_t sbB  = cvta_s(smem + SB_OFF);

    #pragma unroll
    for (int ks = 0; ks < 8; ++ks) {
        uint32_t bf[8][2];
        #pragma unroll
        for (int nt = 0; nt < 8; ++nt)
            ldsm_x2(bf[nt], sbB + bOff + ks * 32 + nt * (8 * ROWB));
        #pragma unroll
        for (int term = 0; term < 2; ++term) {     // A_hi, A_lo
            const uint32_t aBase = (term == 0) ? saHi : saLo;
            #pragma unroll
            for (int ms = 0; ms < 2; ++ms) {
                uint32_t a[4];
                ldsm_x4(a, aBase + aOff + ms * (16 * ROWB) + ks * 32);
                #pragma unroll
                for (int nt = 0; nt < 8; ++nt)
                    mma_f16(acc[ms][nt], a, bf[nt]);
            }
        }
    }

    // ---- Epilogue: add b1 (cols 0..63), direct float2 stores --------------
    const float* b1s = reinterpret_cast<const float*>(smem + SVEC);
    #pragma unroll
    for (int ms = 0; ms < 2; ++ms) {
        const int r0 = m0 + mW + ms * 16 + (lane >> 2);
        #pragma unroll
        for (int nt = 0; nt < 8; ++nt) {
            const int n = n0 + nt * 8 + (lane & 3) * 2;
            float ax = 0.f, ay = 0.f;
            if (nhalf == 0) { ax = b1s[n]; ay = b1s[n + 1]; }
            *reinterpret_cast<float2*>(&g_X[(size_t)r0 * 128 + n]) =
                make_float2(acc[ms][nt][0] + ax, acc[ms][nt][1] + ay);
            *reinterpret_cast<float2*>(&g_X[(size_t)(r0 + 8) * 128 + n]) =
                make_float2(acc[ms][nt][2] + ax, acc[ms][nt][3] + ay);
        }
    }
}

// ======================= Kernel 2: pairwise relu-dot =======================
// Thread-per-output (R6 proven: 46.9us).
#define K2_THREADS 256
#define K2_BT      4
#define XP2        132
#define XT_BYTES   (K2_BT * F_SPARSE * XP2 * 4)   // 54912
#define SW2_OFF    XT_BYTES
#define SLUT_OFF   (SW2_OFF + 256)
#define K2_SMEM    (SLUT_OFF + 328)               // 55496

__global__ void __launch_bounds__(K2_THREADS, 4)
k2_pairs(const float* __restrict__ W2, const float* __restrict__ b2,
         float* __restrict__ out)
{
    extern __shared__ char smem[];
    float* sX = reinterpret_cast<float*>(smem);
    const int tid   = threadIdx.x;
    const int bbase = blockIdx.x * K2_BT;

    for (int idx = tid; idx < K2_BT * F_SPARSE * 32; idx += K2_THREADS) {
        const int r = idx >> 5;
        const int c = idx & 31;
        const int bl = r / F_SPARSE;
        const int f  = r - bl * F_SPARSE;
        const float4 v = reinterpret_cast<const float4*>(
            &g_X[(size_t)(f * BATCH + bbase + bl) * 128])[c];
        *reinterpret_cast<float4*>(sX + r * XP2 + c * 4) = v;
    }
    if (tid < 64)
        reinterpret_cast<float*>(smem + SW2_OFF)[tid] = W2[tid];
    if (tid < F_SPARSE - 1) {
        const int i = tid;
        const int pbase = i * (F_SPARSE - 1) - (i * (i - 1)) / 2;
        const int cnt   = F_SPARSE - 1 - i;
        for (int t = 0; t < cnt; ++t)
            smem[SLUT_OFF + pbase + t] = (char)i;
    }
    const float b2v = b2[0];
    __syncthreads();

    const float4* sW24 = reinterpret_cast<const float4*>(smem + SW2_OFF);

    for (int idx = tid; idx < K2_BT * NPAIR; idx += K2_THREADS) {
        const int bl = idx / NPAIR;
        const int p  = idx - bl * NPAIR;
        const int i  = (int)smem[SLUT_OFF + p];
        const int pbase = i * (F_SPARSE - 1) - (i * (i - 1)) / 2;
        const int j  = i + 1 + (p - pbase);

        const float4* Pa = reinterpret_cast<const float4*>(sX + (bl * F_SPARSE + i) * XP2);
        const float4* Pb = reinterpret_cast<const float4*>(sX + (bl * F_SPARSE + j) * XP2 + 64);

        float a0 = 0.f, a1 = 0.f;
        #pragma unroll
        for (int t = 0; t < 16; ++t) {
            const float4 x = Pa[t];
            const float4 y = Pb[t];
            const float4 w = sW24[t];
            a0 = fmaf(fmaxf(x.x + y.x, 0.f), w.x, a0);
            a1 = fmaf(fmaxf(x.y + y.y, 0.f), w.y, a1);
            a0 = fmaf(fmaxf(x.z + y.z, 0.f), w.z, a0);
            a1 = fmaf(fmaxf(x.w + y.w, 0.f), w.w, a1);
        }
        out[(size_t)(bbase + bl) * NPAIR + p] = a0 + a1 + b2v;
    }
}

// =========================== launcher ======================================
extern "C" void kernel_launch(void* const* d_in, const int* in_sizes, int n_in,
                              void* d_out, int out_size) {
    const float* emb = (const float*)d_in[0];
    const float* W1  = (const float*)d_in[1];
    const float* b1  = (const float*)d_in[2];
    const float* W2  = (const float*)d_in[3];
    const float* b2  = (const float*)d_in[4];
    float* out = (float*)d_out;
    (void)in_sizes; (void)n_in; (void)out_size;

    cudaFuncSetAttribute(k1_gemm,
                         cudaFuncAttributeMaxDynamicSharedMemorySize, K1_SMEM);
    cudaFuncSetAttribute(k2_pairs,
                         cudaFuncAttributeMaxDynamicSharedMemorySize, K2_SMEM);

    k1_gemm<<<M_TOTAL / K1_MT, K1_THREADS, K1_SMEM>>>(emb, W1, b1);
    k2_pairs<<<BATCH / K2_BT, K2_THREADS, K2_SMEM>>>(W2, b2, out);
}

// round 14
// speedup vs baseline: 1.6405x; 1.1337x over previous
#include <cuda_runtime.h>
#include <cuda_fp16.h>
#include <cstdint>

#define F_SPARSE 26
#define BATCH    4096
#define ATT      64
#define NPAIR    325
#define M_TOTAL  (F_SPARSE * BATCH)   // 106496

// fp16 scratch: X[m][128] packed as half2 words, m = f*BATCH + b. 27.25 MB.
__device__ uint32_t g_X[(size_t)M_TOTAL * 64];

// ======================= common helpers ====================================
__device__ __forceinline__ uint32_t cvta_s(const void* p) {
    return (uint32_t)__cvta_generic_to_shared(p);
}
__device__ __forceinline__ void ldsm_x4(uint32_t a[4], uint32_t addr) {
    asm volatile("ldmatrix.sync.aligned.m8n8.x4.shared.b16 {%0,%1,%2,%3}, [%4];"
                 : "=r"(a[0]), "=r"(a[1]), "=r"(a[2]), "=r"(a[3]) : "r"(addr));
}
__device__ __forceinline__ void ldsm_x2(uint32_t b[2], uint32_t addr) {
    asm volatile("ldmatrix.sync.aligned.m8n8.x2.shared.b16 {%0,%1}, [%2];"
                 : "=r"(b[0]), "=r"(b[1]) : "r"(addr));
}
__device__ __forceinline__ void mma_f16(float c[4], const uint32_t a[4], const uint32_t b[2]) {
    asm volatile("mma.sync.aligned.m16n8k16.row.col.f32.f16.f16.f32 "
                 "{%0,%1,%2,%3}, {%4,%5,%6,%7}, {%8,%9}, {%0,%1,%2,%3};"
                 : "+f"(c[0]), "+f"(c[1]), "+f"(c[2]), "+f"(c[3])
                 : "r"(a[0]), "r"(a[1]), "r"(a[2]), "r"(a[3]), "r"(b[0]), "r"(b[1]));
}
__device__ __forceinline__ uint32_t pack_h2(float x, float y) {
    __half2 t; t.x = __float2half(x); t.y = __float2half(y);
    return *reinterpret_cast<uint32_t*>(&t);
}

// ======================= Kernel 1: X = E @ W1c (+b1) =======================
// fp16 2-term split: X = A_hi@B + A_lo@B. CTA = 256 M-rows, 512 threads,
// 16 warps of m32n64, B fragments hoisted. X stored fp16.
#define K1_MT      256
#define K1_THREADS 512
#define ROWB       272                 // 128 fp16 + 8 pad, bytes
#define SA_HI      0
#define SA_SZ      (K1_MT * ROWB)      // 69632
#define SA_LO      (SA_HI + SA_SZ)
#define SB_OFF     (SA_LO + SA_SZ)     // 139264
#define SB_SZ      (128 * ROWB)        // 34816
#define SVEC       (SB_OFF + SB_SZ)    // 174080 : b1 (64 f32)
#define K1_SMEM    (SVEC + 256)        // 174336

__global__ void __launch_bounds__(K1_THREADS, 1)
k1_gemm(const float* __restrict__ emb, const float* __restrict__ W1,
        const float* __restrict__ b1)
{
    extern __shared__ char smem[];
    const int tid  = threadIdx.x;
    const int lane = tid & 31;
    const int warp = tid >> 5;
    const int m0   = blockIdx.x * K1_MT;

    // ---- A fill: 256 contiguous rows of emb -> fp16 hi/lo -----------------
    for (int idx = tid; idx < K1_MT * 32; idx += K1_THREADS) {
        const int r = idx >> 5;
        const int c = idx & 31;                       // k = 4c
        const float4 v = reinterpret_cast<const float4*>(emb)[(size_t)(m0 + r) * 32 + c];
        float vv[4] = {v.x, v.y, v.z, v.w};
        float hv[4];
        #pragma unroll
        for (int q = 0; q < 4; ++q)
            hv[q] = __half2float(__float2half(vv[q]));
        *reinterpret_cast<uint2*>(smem + SA_HI + r * ROWB + c * 8) =
            make_uint2(pack_h2(vv[0], vv[1]), pack_h2(vv[2], vv[3]));
        *reinterpret_cast<uint2*>(smem + SA_LO + r * ROWB + c * 8) =
            make_uint2(pack_h2(vv[0]-hv[0], vv[1]-hv[1]), pack_h2(vv[2]-hv[2], vv[3]-hv[3]));
    }
    // ---- B fill: W1c stored [n][k], fp16 single ---------------------------
    for (int idx = tid; idx < 128 * 32; idx += K1_THREADS) {
        const int n = idx >> 5;
        const int c = idx & 31;
        const int k = c * 4;
        const int rs = (n < 64) ? k : (128 + k);
        const int cs = n & 63;
        float vv[4];
        #pragma unroll
        for (int q = 0; q < 4; ++q)
            vv[q] = W1[(size_t)(rs + q) * ATT + cs];
        *reinterpret_cast<uint2*>(smem + SB_OFF + n * ROWB + k * 2) =
            make_uint2(pack_h2(vv[0], vv[1]), pack_h2(vv[2], vv[3]));
    }
    if (tid < 64)
        reinterpret_cast<float*>(smem + SVEC)[tid] = b1[tid];
    __syncthreads();

    // ---- MMA: 16 warps = 8 m32-subtiles x 2 n64-halves --------------------
    const int msub32 = warp >> 1;
    const int nhalf  = warp & 1;
    const int mW     = msub32 * 32;
    const int n0     = nhalf * 64;

    float acc[2][8][4];
    #pragma unroll
    for (int ms = 0; ms < 2; ++ms)
        #pragma unroll
        for (int nt = 0; nt < 8; ++nt) {
            acc[ms][nt][0]=0.f; acc[ms][nt][1]=0.f; acc[ms][nt][2]=0.f; acc[ms][nt][3]=0.f;
        }

    const int midx = lane >> 3;
    const uint32_t aOff = (uint32_t)((mW + ((midx & 1) << 3) + (lane & 7)) * ROWB
                                     + ((midx >> 1) << 4));
    const uint32_t bOff = (uint32_t)((n0 + (lane & 7)) * ROWB + (((lane >> 3) & 1) << 4));
    const uint32_t saHi = cvta_s(smem + SA_HI);
    const uint32_t saLo = cvta_s(smem + SA_LO);
    const uint32_t sbB  = cvta_s(smem + SB_OFF);

    #pragma unroll
    for (int ks = 0; ks < 8; ++ks) {
        uint32_t bf[8][2];
        #pragma unroll
        for (int nt = 0; nt < 8; ++nt)
            ldsm_x2(bf[nt], sbB + bOff + ks * 32 + nt * (8 * ROWB));
        #pragma unroll
        for (int term = 0; term < 2; ++term) {
            const uint32_t aBase = (term == 0) ? saHi : saLo;
            #pragma unroll
            for (int ms = 0; ms < 2; ++ms) {
                uint32_t a[4];
                ldsm_x4(a, aBase + aOff + ms * (16 * ROWB) + ks * 32);
                #pragma unroll
                for (int nt = 0; nt < 8; ++nt)
                    mma_f16(acc[ms][nt], a, bf[nt]);
            }
        }
    }

    // ---- Epilogue: +b1 (cols 0..63), pack fp16, store half2 words ---------
    const float* b1s = reinterpret_cast<const float*>(smem + SVEC);
    #pragma unroll
    for (int ms = 0; ms < 2; ++ms) {
        const int r0 = m0 + mW + ms * 16 + (lane >> 2);
        #pragma unroll
        for (int nt = 0; nt < 8; ++nt) {
            const int n = n0 + nt * 8 + (lane & 3) * 2;
            float ax = 0.f, ay = 0.f;
            if (nhalf == 0) { ax = b1s[n]; ay = b1s[n + 1]; }
            g_X[(size_t)r0 * 64 + (n >> 1)] =
                pack_h2(acc[ms][nt][0] + ax, acc[ms][nt][1] + ay);
            g_X[(size_t)(r0 + 8) * 64 + (n >> 1)] =
                pack_h2(acc[ms][nt][2] + ax, acc[ms][nt][3] + ay);
        }
    }
}

// ======================= Kernel 2: pairwise relu-dot =======================
// X tile fp16 (half the LDS bytes), half2 add+relu, fp32 dot with W2.
#define K2_THREADS 256
#define K2_BT      4
#define XPH        68                                  // uint32 pitch per row
#define XT_BYTES   (K2_BT * F_SPARSE * XPH * 4)        // 28288
#define SW2_OFF    XT_BYTES
#define SLUT_OFF   (SW2_OFF + 256)
#define K2_SMEM    (SLUT_OFF + 328)                    // 28872

__global__ void __launch_bounds__(K2_THREADS, 6)
k2_pairs(const float* __restrict__ W2, const float* __restrict__ b2,
         float* __restrict__ out)
{
    extern __shared__ char smem[];
    uint32_t* sX = reinterpret_cast<uint32_t*>(smem);
    const int tid   = threadIdx.x;
    const int bbase = blockIdx.x * K2_BT;

    // ---- X tile load: rows r = bl*26 + f, 16 uint4 per row ----------------
    for (int idx = tid; idx < K2_BT * F_SPARSE * 16; idx += K2_THREADS) {
        const int r = idx >> 4;
        const int c = idx & 15;
        const int bl = r / F_SPARSE;
        const int f  = r - bl * F_SPARSE;
        const uint4 v = reinterpret_cast<const uint4*>(
            &g_X[(size_t)(f * BATCH + bbase + bl) * 64])[c];
        *reinterpret_cast<uint4*>(sX + r * XPH + c * 4) = v;
    }
    if (tid < 64)
        reinterpret_cast<float*>(smem + SW2_OFF)[tid] = W2[tid];
    if (tid < F_SPARSE - 1) {
        const int i = tid;
        const int pbase = i * (F_SPARSE - 1) - (i * (i - 1)) / 2;
        const int cnt   = F_SPARSE - 1 - i;
        for (int t = 0; t < cnt; ++t)
            smem[SLUT_OFF + pbase + t] = (char)i;
    }
    const float b2v = b2[0];
    __syncthreads();

    const float4* sW24 = reinterpret_cast<const float4*>(smem + SW2_OFF);
    const __half2 zero2 = __float2half2_rn(0.f);

    for (int idx = tid; idx < K2_BT * NPAIR; idx += K2_THREADS) {
        const int bl = idx / NPAIR;
        const int p  = idx - bl * NPAIR;
        const int i  = (int)smem[SLUT_OFF + p];
        const int pbase = i * (F_SPARSE - 1) - (i * (i - 1)) / 2;
        const int j  = i + 1 + (p - pbase);

        const uint4* Pa = reinterpret_cast<const uint4*>(sX + (bl * F_SPARSE + i) * XPH);
        const uint4* Pb = reinterpret_cast<const uint4*>(sX + (bl * F_SPARSE + j) * XPH + 32);

        float a0 = 0.f, a1 = 0.f;
        #pragma unroll
        for (int t = 0; t < 8; ++t) {                   // 8 halves per iter
            const uint4 xa = Pa[t];
            const uint4 xb = Pb[t];
            const float4 w0 = sW24[t * 2];
            const float4 w1 = sW24[t * 2 + 1];
            const uint32_t av[4] = {xa.x, xa.y, xa.z, xa.w};
            const uint32_t bv[4] = {xb.x, xb.y, xb.z, xb.w};
            float2 f[4];
            #pragma unroll
            for (int q = 0; q < 4; ++q) {
                const __half2 ha = *reinterpret_cast<const __half2*>(&av[q]);
                const __half2 hb = *reinterpret_cast<const __half2*>(&bv[q]);
                const __half2 s  = __hmax2(__hadd2(ha, hb), zero2);
                f[q] = __half22float2(s);
            }
            a0 = fmaf(f[0].x, w0.x, a0);  a1 = fmaf(f[0].y, w0.y, a1);
            a0 = fmaf(f[1].x, w0.z, a0);  a1 = fmaf(f[1].y, w0.w, a1);
            a0 = fmaf(f[2].x, w1.x, a0);  a1 = fmaf(f[2].y, w1.y, a1);
            a0 = fmaf(f[3].x, w1.z, a0);  a1 = fmaf(f[3].y, w1.w, a1);
        }
        out[(size_t)(bbase + bl) * NPAIR + p] = a0 + a1 + b2v;
    }
}

// =========================== launcher ======================================
extern "C" void kernel_launch(void* const* d_in, const int* in_sizes, int n_in,
                              void* d_out, int out_size) {
    const float* emb = (const float*)d_in[0];
    const float* W1  = (const float*)d_in[1];
    const float* b1  = (const float*)d_in[2];
    const float* W2  = (const float*)d_in[3];
    const float* b2  = (const float*)d_in[4];
    float* out = (float*)d_out;
    (void)in_sizes; (void)n_in; (void)out_size;

    cudaFuncSetAttribute(k1_gemm,
                         cudaFuncAttributeMaxDynamicSharedMemorySize, K1_SMEM);
    cudaFuncSetAttribute(k2_pairs,
                         cudaFuncAttributeMaxDynamicSharedMemorySize, K2_SMEM);

    k1_gemm<<<M_TOTAL / K1_MT, K1_THREADS, K1_SMEM>>>(emb, W1, b1);
    k2_pairs<<<BATCH / K2_BT, K2_THREADS, K2_SMEM>>>(W2, b2, out);
}

// round 15
// speedup vs baseline: 1.7494x; 1.0664x over previous
#include <cuda_runtime.h>
#include <cuda_fp16.h>
#include <cstdint>

#define F_SPARSE 26
#define BATCH    4096
#define ATT      64
#define NPAIR    325
#define M_TOTAL  (F_SPARSE * BATCH)   // 106496

// fp16 scratch: X[m][128] packed as half2 words, m = f*BATCH + b. 27.25 MB.
__device__ uint32_t g_X[(size_t)M_TOTAL * 64];

// ======================= common helpers ====================================
__device__ __forceinline__ uint32_t cvta_s(const void* p) {
    return (uint32_t)__cvta_generic_to_shared(p);
}
__device__ __forceinline__ void ldsm_x4(uint32_t a[4], uint32_t addr) {
    asm volatile("ldmatrix.sync.aligned.m8n8.x4.shared.b16 {%0,%1,%2,%3}, [%4];"
                 : "=r"(a[0]), "=r"(a[1]), "=r"(a[2]), "=r"(a[3]) : "r"(addr));
}
__device__ __forceinline__ void ldsm_x2(uint32_t b[2], uint32_t addr) {
    asm volatile("ldmatrix.sync.aligned.m8n8.x2.shared.b16 {%0,%1}, [%2];"
                 : "=r"(b[0]), "=r"(b[1]) : "r"(addr));
}
__device__ __forceinline__ void mma_f16(float c[4], const uint32_t a[4], const uint32_t b[2]) {
    asm volatile("mma.sync.aligned.m16n8k16.row.col.f32.f16.f16.f32 "
                 "{%0,%1,%2,%3}, {%4,%5,%6,%7}, {%8,%9}, {%0,%1,%2,%3};"
                 : "+f"(c[0]), "+f"(c[1]), "+f"(c[2]), "+f"(c[3])
                 : "r"(a[0]), "r"(a[1]), "r"(a[2]), "r"(a[3]), "r"(b[0]), "r"(b[1]));
}
__device__ __forceinline__ uint32_t pack_h2(float x, float y) {
    __half2 t; t.x = __float2half(x); t.y = __float2half(y);
    return *reinterpret_cast<uint32_t*>(&t);
}

// ======================= Kernel 1: X = E @ W1c (+b1) =======================
// Single fp16 pass (A and B both fp16; validated components: B-round 2.1e-4,
// X-store 3.1e-4; predicted total ~4.3e-4). CTA = 256 M-rows, 512 threads,
// 16 warps of m32n64, B fragments hoisted. X stored fp16.
#define K1_MT      256
#define K1_THREADS 512
#define ROWB       272                 // 128 fp16 + 8 pad, bytes
#define SA_OFF     0
#define SA_SZ      (K1_MT * ROWB)      // 69632
#define SB_OFF     (SA_OFF + SA_SZ)    // 69632
#define SB_SZ      (128 * ROWB)        // 34816
#define SVEC       (SB_OFF + SB_SZ)    // 104448 : b1 (64 f32)
#define K1_SMEM    (SVEC + 256)        // 104704

__global__ void __launch_bounds__(K1_THREADS, 1)
k1_gemm(const float* __restrict__ emb, const float* __restrict__ W1,
        const float* __restrict__ b1)
{
    extern __shared__ char smem[];
    const int tid  = threadIdx.x;
    const int lane = tid & 31;
    const int warp = tid >> 5;
    const int m0   = blockIdx.x * K1_MT;

    // ---- A fill: 256 contiguous rows of emb -> fp16 ----------------------
    for (int idx = tid; idx < K1_MT * 32; idx += K1_THREADS) {
        const int r = idx >> 5;
        const int c = idx & 31;                       // k = 4c
        const float4 v = reinterpret_cast<const float4*>(emb)[(size_t)(m0 + r) * 32 + c];
        *reinterpret_cast<uint2*>(smem + SA_OFF + r * ROWB + c * 8) =
            make_uint2(pack_h2(v.x, v.y), pack_h2(v.z, v.w));
    }
    // ---- B fill: W1c stored [n][k], fp16 ----------------------------------
    // n<64 -> W1[k][n] ; n>=64 -> W1[128+k][n-64]
    for (int idx = tid; idx < 128 * 32; idx += K1_THREADS) {
        const int n = idx >> 5;
        const int c = idx & 31;
        const int k = c * 4;
        const int rs = (n < 64) ? k : (128 + k);
        const int cs = n & 63;
        float vv[4];
        #pragma unroll
        for (int q = 0; q < 4; ++q)
            vv[q] = W1[(size_t)(rs + q) * ATT + cs];
        *reinterpret_cast<uint2*>(smem + SB_OFF + n * ROWB + k * 2) =
            make_uint2(pack_h2(vv[0], vv[1]), pack_h2(vv[2], vv[3]));
    }
    if (tid < 64)
        reinterpret_cast<float*>(smem + SVEC)[tid] = b1[tid];
    __syncthreads();

    // ---- MMA: 16 warps = 8 m32-subtiles x 2 n64-halves, single pass -------
    const int msub32 = warp >> 1;
    const int nhalf  = warp & 1;
    const int mW     = msub32 * 32;
    const int n0     = nhalf * 64;

    float acc[2][8][4];
    #pragma unroll
    for (int ms = 0; ms < 2; ++ms)
        #pragma unroll
        for (int nt = 0; nt < 8; ++nt) {
            acc[ms][nt][0]=0.f; acc[ms][nt][1]=0.f; acc[ms][nt][2]=0.f; acc[ms][nt][3]=0.f;
        }

    const int midx = lane >> 3;
    const uint32_t aOff = (uint32_t)((mW + ((midx & 1) << 3) + (lane & 7)) * ROWB
                                     + ((midx >> 1) << 4));
    const uint32_t bOff = (uint32_t)((n0 + (lane & 7)) * ROWB + (((lane >> 3) & 1) << 4));
    const uint32_t saB = cvta_s(smem + SA_OFF);
    const uint32_t sbB = cvta_s(smem + SB_OFF);

    #pragma unroll
    for (int ks = 0; ks < 8; ++ks) {
        uint32_t bf[8][2];
        #pragma unroll
        for (int nt = 0; nt < 8; ++nt)
            ldsm_x2(bf[nt], sbB + bOff + ks * 32 + nt * (8 * ROWB));
        #pragma unroll
        for (int ms = 0; ms < 2; ++ms) {
            uint32_t a[4];
            ldsm_x4(a, saB + aOff + ms * (16 * ROWB) + ks * 32);
            #pragma unroll
            for (int nt = 0; nt < 8; ++nt)
                mma_f16(acc[ms][nt], a, bf[nt]);
        }
    }

    // ---- Epilogue: +b1 (cols 0..63), pack fp16, store half2 words ---------
    const float* b1s = reinterpret_cast<const float*>(smem + SVEC);
    #pragma unroll
    for (int ms = 0; ms < 2; ++ms) {
        const int r0 = m0 + mW + ms * 16 + (lane >> 2);
        #pragma unroll
        for (int nt = 0; nt < 8; ++nt) {
            const int n = n0 + nt * 8 + (lane & 3) * 2;
            float ax = 0.f, ay = 0.f;
            if (nhalf == 0) { ax = b1s[n]; ay = b1s[n + 1]; }
            g_X[(size_t)r0 * 64 + (n >> 1)] =
                pack_h2(acc[ms][nt][0] + ax, acc[ms][nt][1] + ay);
            g_X[(size_t)(r0 + 8) * 64 + (n >> 1)] =
                pack_h2(acc[ms][nt][2] + ax, acc[ms][nt][3] + ay);
        }
    }
}

// ======================= Kernel 2: pairwise relu-dot =======================
// X tile fp16, half2 add+relu, fp32 dot with W2. (R13 proven: 32.8us)
#define K2_THREADS 256
#define K2_BT      4
#define XPH        68                                  // uint32 pitch per row
#define XT_BYTES   (K2_BT * F_SPARSE * XPH * 4)        // 28288
#define SW2_OFF    XT_BYTES
#define SLUT_OFF   (SW2_OFF + 256)
#define K2_SMEM    (SLUT_OFF + 328)                    // 28872

__global__ void __launch_bounds__(K2_THREADS, 6)
k2_pairs(const float* __restrict__ W2, const float* __restrict__ b2,
         float* __restrict__ out)
{
    extern __shared__ char smem[];
    uint32_t* sX = reinterpret_cast<uint32_t*>(smem);
    const int tid   = threadIdx.x;
    const int bbase = blockIdx.x * K2_BT;

    for (int idx = tid; idx < K2_BT * F_SPARSE * 16; idx += K2_THREADS) {
        const int r = idx >> 4;
        const int c = idx & 15;
        const int bl = r / F_SPARSE;
        const int f  = r - bl * F_SPARSE;
        const uint4 v = reinterpret_cast<const uint4*>(
            &g_X[(size_t)(f * BATCH + bbase + bl) * 64])[c];
        *reinterpret_cast<uint4*>(sX + r * XPH + c * 4) = v;
    }
    if (tid < 64)
        reinterpret_cast<float*>(smem + SW2_OFF)[tid] = W2[tid];
    if (tid < F_SPARSE - 1) {
        const int i = tid;
        const int pbase = i * (F_SPARSE - 1) - (i * (i - 1)) / 2;
        const int cnt   = F_SPARSE - 1 - i;
        for (int t = 0; t < cnt; ++t)
            smem[SLUT_OFF + pbase + t] = (char)i;
    }
    const float b2v = b2[0];
    __syncthreads();

    const float4* sW24 = reinterpret_cast<const float4*>(smem + SW2_OFF);
    const __half2 zero2 = __float2half2_rn(0.f);

    for (int idx = tid; idx < K2_BT * NPAIR; idx += K2_THREADS) {
        const int bl = idx / NPAIR;
        const int p  = idx - bl * NPAIR;
        const int i  = (int)smem[SLUT_OFF + p];
        const int pbase = i * (F_SPARSE - 1) - (i * (i - 1)) / 2;
        const int j  = i + 1 + (p - pbase);

        const uint4* Pa = reinterpret_cast<const uint4*>(sX + (bl * F_SPARSE + i) * XPH);
        const uint4* Pb = reinterpret_cast<const uint4*>(sX + (bl * F_SPARSE + j) * XPH + 32);

        float a0 = 0.f, a1 = 0.f;
        #pragma unroll
        for (int t = 0; t < 8; ++t) {
            const uint4 xa = Pa[t];
            const uint4 xb = Pb[t];
            const float4 w0 = sW24[t * 2];
            const float4 w1 = sW24[t * 2 + 1];
            const uint32_t av[4] = {xa.x, xa.y, xa.z, xa.w};
            const uint32_t bv[4] = {xb.x, xb.y, xb.z, xb.w};
            float2 f[4];
            #pragma unroll
            for (int q = 0; q < 4; ++q) {
                const __half2 ha = *reinterpret_cast<const __half2*>(&av[q]);
                const __half2 hb = *reinterpret_cast<const __half2*>(&bv[q]);
                const __half2 s  = __hmax2(__hadd2(ha, hb), zero2);
                f[q] = __half22float2(s);
            }
            a0 = fmaf(f[0].x, w0.x, a0);  a1 = fmaf(f[0].y, w0.y, a1);
            a0 = fmaf(f[1].x, w0.z, a0);  a1 = fmaf(f[1].y, w0.w, a1);
            a0 = fmaf(f[2].x, w1.x, a0);  a1 = fmaf(f[2].y, w1.y, a1);
            a0 = fmaf(f[3].x, w1.z, a0);  a1 = fmaf(f[3].y, w1.w, a1);
        }
        out[(size_t)(bbase + bl) * NPAIR + p] = a0 + a1 + b2v;
    }
}

// =========================== launcher ======================================
extern "C" void kernel_launch(void* const* d_in, const int* in_sizes, int n_in,
                              void* d_out, int out_size) {
    const float* emb = (const float*)d_in[0];
    const float* W1  = (const float*)d_in[1];
    const float* b1  = (const float*)d_in[2];
    const float* W2  = (const float*)d_in[3];
    const float* b2  = (const float*)d_in[4];
    float* out = (float*)d_out;
    (void)in_sizes; (void)n_in; (void)out_size;

    cudaFuncSetAttribute(k1_gemm,
                         cudaFuncAttributeMaxDynamicSharedMemorySize, K1_SMEM);
    cudaFuncSetAttribute(k2_pairs,
                         cudaFuncAttributeMaxDynamicSharedMemorySize, K2_SMEM);

    k1_gemm<<<M_TOTAL / K1_MT, K1_THREADS, K1_SMEM>>>(emb, W1, b1);
    k2_pairs<<<BATCH / K2_BT, K2_THREADS, K2_SMEM>>>(W2, b2, out);
}

// round 16
// speedup vs baseline: 2.0000x; 1.1432x over previous
#include <cuda_runtime.h>
#include <cuda_fp16.h>
#include <cstdint>

#define F_SPARSE 26
#define BATCH    4096
#define ATT      64
#define NPAIR    325
#define M_TOTAL  (F_SPARSE * BATCH)   // 106496

// fp16 scratch: X[m][128] packed as half2 words, m = f*BATCH + b. 27.25 MB.
__device__ uint32_t g_X[(size_t)M_TOTAL * 64];

// ======================= common helpers ====================================
__device__ __forceinline__ uint32_t cvta_s(const void* p) {
    return (uint32_t)__cvta_generic_to_shared(p);
}
__device__ __forceinline__ void ldsm_x2(uint32_t b[2], uint32_t addr) {
    asm volatile("ldmatrix.sync.aligned.m8n8.x2.shared.b16 {%0,%1}, [%2];"
                 : "=r"(b[0]), "=r"(b[1]) : "r"(addr));
}
__device__ __forceinline__ void mma_f16(float c[4], const uint32_t a[4], const uint32_t b[2]) {
    asm volatile("mma.sync.aligned.m16n8k16.row.col.f32.f16.f16.f32 "
                 "{%0,%1,%2,%3}, {%4,%5,%6,%7}, {%8,%9}, {%0,%1,%2,%3};"
                 : "+f"(c[0]), "+f"(c[1]), "+f"(c[2]), "+f"(c[3])
                 : "r"(a[0]), "r"(a[1]), "r"(a[2]), "r"(a[3]), "r"(b[0]), "r"(b[1]));
}
__device__ __forceinline__ uint32_t pack_h2(float x, float y) {
    __half2 t = __floats2half2_rn(x, y);
    return *reinterpret_cast<uint32_t*>(&t);
}

// ======================= Kernel 1: X = E @ W1c (+b1) =======================
// Single fp16 pass. A fragments loaded DIRECTLY from global (no smem staging,
// no fill barrier): 4x LDG.64 + 4x f32x2->f16x2 per fragment, fully unrolled
// for MLP. B (64 KB->35 KB smem) via LDSM as before. X stored fp16.
#define K1_MT      256
#define K1_THREADS 512
#define ROWB       272                 // 128 fp16 + 8 pad, bytes
#define SB_OFF     0
#define SB_SZ      (128 * ROWB)        // 34816
#define SVEC       (SB_OFF + SB_SZ)    // 34816 : b1 (64 f32)
#define K1_SMEM    (SVEC + 256)        // 35072

__global__ void __launch_bounds__(K1_THREADS, 1)
k1_gemm(const float* __restrict__ emb, const float* __restrict__ W1,
        const float* __restrict__ b1)
{
    extern __shared__ char smem[];
    const int tid  = threadIdx.x;
    const int lane = tid & 31;
    const int warp = tid >> 5;
    const int m0   = blockIdx.x * K1_MT;

    // ---- B fill: W1c stored [n][k], fp16 ----------------------------------
    // n<64 -> W1[k][n] ; n>=64 -> W1[128+k][n-64]
    for (int idx = tid; idx < 128 * 32; idx += K1_THREADS) {
        const int n = idx >> 5;
        const int c = idx & 31;
        const int k = c * 4;
        const int rs = (n < 64) ? k : (128 + k);
        const int cs = n & 63;
        float vv[4];
        #pragma unroll
        for (int q = 0; q < 4; ++q)
            vv[q] = W1[(size_t)(rs + q) * ATT + cs];
        *reinterpret_cast<uint2*>(smem + SB_OFF + n * ROWB + k * 2) =
            make_uint2(pack_h2(vv[0], vv[1]), pack_h2(vv[2], vv[3]));
    }
    if (tid < 64)
        reinterpret_cast<float*>(smem + SVEC)[tid] = b1[tid];
    __syncthreads();

    // ---- MMA: 16 warps = 8 m32-subtiles x 2 n64-halves --------------------
    const int msub32 = warp >> 1;
    const int nhalf  = warp & 1;
    const int mW     = msub32 * 32;
    const int n0     = nhalf * 64;

    float acc[2][8][4];
    #pragma unroll
    for (int ms = 0; ms < 2; ++ms)
        #pragma unroll
        for (int nt = 0; nt < 8; ++nt) {
            acc[ms][nt][0]=0.f; acc[ms][nt][1]=0.f; acc[ms][nt][2]=0.f; acc[ms][nt][3]=0.f;
        }

    const uint32_t bOff = (uint32_t)((n0 + (lane & 7)) * ROWB + (((lane >> 3) & 1) << 4));
    const uint32_t sbB  = cvta_s(smem + SB_OFF);

    // A fragment base pointers: rows m0+mW+ms*16+(lane>>2) and +8,
    // cols ks*16 + (lane&3)*2 (+8 for the k-high matrices).
    const float* aBase0 = emb + (size_t)(m0 + mW + (lane >> 2)) * 128 + (lane & 3) * 2;
    const float* aBase1 = aBase0 + 16 * 128;      // ms=1

    #pragma unroll
    for (int ks = 0; ks < 8; ++ks) {
        uint32_t bf[8][2];
        #pragma unroll
        for (int nt = 0; nt < 8; ++nt)
            ldsm_x2(bf[nt], sbB + bOff + ks * 32 + nt * (8 * ROWB));
        #pragma unroll
        for (int ms = 0; ms < 2; ++ms) {
            const float* bp = (ms == 0 ? aBase0 : aBase1) + ks * 16;
            const float2 v0 = *reinterpret_cast<const float2*>(bp);              // a0
            const float2 v1 = *reinterpret_cast<const float2*>(bp + 8 * 128);    // a1
            const float2 v2 = *reinterpret_cast<const float2*>(bp + 8);          // a2
            const float2 v3 = *reinterpret_cast<const float2*>(bp + 8 * 128 + 8);// a3
            uint32_t a[4];
            a[0] = pack_h2(v0.x, v0.y);
            a[1] = pack_h2(v1.x, v1.y);
            a[2] = pack_h2(v2.x, v2.y);
            a[3] = pack_h2(v3.x, v3.y);
            #pragma unroll
            for (int nt = 0; nt < 8; ++nt)
                mma_f16(acc[ms][nt], a, bf[nt]);
        }
    }

    // ---- Epilogue: +b1 (cols 0..63), pack fp16, store half2 words ---------
    const float* b1s = reinterpret_cast<const float*>(smem + SVEC);
    #pragma unroll
    for (int ms = 0; ms < 2; ++ms) {
        const int r0 = m0 + mW + ms * 16 + (lane >> 2);
        #pragma unroll
        for (int nt = 0; nt < 8; ++nt) {
            const int n = n0 + nt * 8 + (lane & 3) * 2;
            float ax = 0.f, ay = 0.f;
            if (nhalf == 0) { ax = b1s[n]; ay = b1s[n + 1]; }
            g_X[(size_t)r0 * 64 + (n >> 1)] =
                pack_h2(acc[ms][nt][0] + ax, acc[ms][nt][1] + ay);
            g_X[(size_t)(r0 + 8) * 64 + (n >> 1)] =
                pack_h2(acc[ms][nt][2] + ax, acc[ms][nt][3] + ay);
        }
    }
}

// ======================= Kernel 2: pairwise relu-dot =======================
// X tile fp16, half2 add+relu, fp32 dot with W2. (R13/R14 proven: 32.7us)
#define K2_THREADS 256
#define K2_BT      4
#define XPH        68                                  // uint32 pitch per row
#define XT_BYTES   (K2_BT * F_SPARSE * XPH * 4)        // 28288
#define SW2_OFF    XT_BYTES
#define SLUT_OFF   (SW2_OFF + 256)
#define K2_SMEM    (SLUT_OFF + 328)                    // 28872

__global__ void __launch_bounds__(K2_THREADS, 6)
k2_pairs(const float* __restrict__ W2, const float* __restrict__ b2,
         float* __restrict__ out)
{
    extern __shared__ char smem[];
    uint32_t* sX = reinterpret_cast<uint32_t*>(smem);
    const int tid   = threadIdx.x;
    const int bbase = blockIdx.x * K2_BT;

    for (int idx = tid; idx < K2_BT * F_SPARSE * 16; idx += K2_THREADS) {
        const int r = idx >> 4;
        const int c = idx & 15;
        const int bl = r / F_SPARSE;
        const int f  = r - bl * F_SPARSE;
        const uint4 v = reinterpret_cast<const uint4*>(
            &g_X[(size_t)(f * BATCH + bbase + bl) * 64])[c];
        *reinterpret_cast<uint4*>(sX + r * XPH + c * 4) = v;
    }
    if (tid < 64)
        reinterpret_cast<float*>(smem + SW2_OFF)[tid] = W2[tid];
    if (tid < F_SPARSE - 1) {
        const int i = tid;
        const int pbase = i * (F_SPARSE - 1) - (i * (i - 1)) / 2;
        const int cnt   = F_SPARSE - 1 - i;
        for (int t = 0; t < cnt; ++t)
            smem[SLUT_OFF + pbase + t] = (char)i;
    }
    const float b2v = b2[0];
    __syncthreads();

    const float4* sW24 = reinterpret_cast<const float4*>(smem + SW2_OFF);
    const __half2 zero2 = __float2half2_rn(0.f);

    for (int idx = tid; idx < K2_BT * NPAIR; idx += K2_THREADS) {
        const int bl = idx / NPAIR;
        const int p  = idx - bl * NPAIR;
        const int i  = (int)smem[SLUT_OFF + p];
        const int pbase = i * (F_SPARSE - 1) - (i * (i - 1)) / 2;
        const int j  = i + 1 + (p - pbase);

        const uint4* Pa = reinterpret_cast<const uint4*>(sX + (bl * F_SPARSE + i) * XPH);
        const uint4* Pb = reinterpret_cast<const uint4*>(sX + (bl * F_SPARSE + j) * XPH + 32);

        float a0 = 0.f, a1 = 0.f;
        #pragma unroll
        for (int t = 0; t < 8; ++t) {
            const uint4 xa = Pa[t];
            const uint4 xb = Pb[t];
            const float4 w0 = sW24[t * 2];
            const float4 w1 = sW24[t * 2 + 1];
            const uint32_t av[4] = {xa.x, xa.y, xa.z, xa.w};
            const uint32_t bv[4] = {xb.x, xb.y, xb.z, xb.w};
            float2 f[4];
            #pragma unroll
            for (int q = 0; q < 4; ++q) {
                const __half2 ha = *reinterpret_cast<const __half2*>(&av[q]);
                const __half2 hb = *reinterpret_cast<const __half2*>(&bv[q]);
                const __half2 s  = __hmax2(__hadd2(ha, hb), zero2);
                f[q] = __half22float2(s);
            }
            a0 = fmaf(f[0].x, w0.x, a0);  a1 = fmaf(f[0].y, w0.y, a1);
            a0 = fmaf(f[1].x, w0.z, a0);  a1 = fmaf(f[1].y, w0.w, a1);
            a0 = fmaf(f[2].x, w1.x, a0);  a1 = fmaf(f[2].y, w1.y, a1);
            a0 = fmaf(f[3].x, w1.z, a0);  a1 = fmaf(f[3].y, w1.w, a1);
        }
        out[(size_t)(bbase + bl) * NPAIR + p] = a0 + a1 + b2v;
    }
}

// =========================== launcher ======================================
extern "C" void kernel_launch(void* const* d_in, const int* in_sizes, int n_in,
                              void* d_out, int out_size) {
    const float* emb = (const float*)d_in[0];
    const float* W1  = (const float*)d_in[1];
    const float* b1  = (const float*)d_in[2];
    const float* W2  = (const float*)d_in[3];
    const float* b2  = (const float*)d_in[4];
    float* out = (float*)d_out;
    (void)in_sizes; (void)n_in; (void)out_size;

    cudaFuncSetAttribute(k1_gemm,
                         cudaFuncAttributeMaxDynamicSharedMemorySize, K1_SMEM);
    cudaFuncSetAttribute(k2_pairs,
                         cudaFuncAttributeMaxDynamicSharedMemorySize, K2_SMEM);

    k1_gemm<<<M_TOTAL / K1_MT, K1_THREADS, K1_SMEM>>>(emb, W1, b1);
    k2_pairs<<<BATCH / K2_BT, K2_THREADS, K2_SMEM>>>(W2, b2, out);
}

// round 17
// speedup vs baseline: 2.0488x; 1.0244x over previous
#include <cuda_runtime.h>
#include <cuda_fp16.h>
#include <cstdint>

#define F_SPARSE 26
#define BATCH    4096
#define ATT      64
#define NPAIR    325
#define M_TOTAL  (F_SPARSE * BATCH)   // 106496

// fp16 scratch: X[m][128] packed as half2 words, m = f*BATCH + b. 27.25 MB.
__device__ uint32_t g_X[(size_t)M_TOTAL * 64];

// ======================= common helpers ====================================
__device__ __forceinline__ uint32_t cvta_s(const void* p) {
    return (uint32_t)__cvta_generic_to_shared(p);
}
__device__ __forceinline__ void ldsm_x2(uint32_t b[2], uint32_t addr) {
    asm volatile("ldmatrix.sync.aligned.m8n8.x2.shared.b16 {%0,%1}, [%2];"
                 : "=r"(b[0]), "=r"(b[1]) : "r"(addr));
}
__device__ __forceinline__ void mma_f16(float c[4], const uint32_t a[4], const uint32_t b[2]) {
    asm volatile("mma.sync.aligned.m16n8k16.row.col.f32.f16.f16.f32 "
                 "{%0,%1,%2,%3}, {%4,%5,%6,%7}, {%8,%9}, {%0,%1,%2,%3};"
                 : "+f"(c[0]), "+f"(c[1]), "+f"(c[2]), "+f"(c[3])
                 : "r"(a[0]), "r"(a[1]), "r"(a[2]), "r"(a[3]), "r"(b[0]), "r"(b[1]));
}
__device__ __forceinline__ uint32_t pack_h2(float x, float y) {
    __half2 t = __floats2half2_rn(x, y);
    return *reinterpret_cast<uint32_t*>(&t);
}

// ======================= Kernel 1: X = E @ W1c (+b1) =======================
// Single fp16 pass. Warp = one m16 tile x FULL N=128: A fragments loaded
// once (not twice), 8 fragments/warp, one-ks-ahead prefetch hides LDG->cvt.
// B via smem LDSM. X stored fp16.
#define K1_MT      256
#define K1_THREADS 512
#define ROWB       272                 // 128 fp16 + 8 pad, bytes
#define SB_OFF     0
#define SB_SZ      (128 * ROWB)        // 34816
#define SVEC       (SB_OFF + SB_SZ)    // 34816 : b1 (64 f32)
#define K1_SMEM    (SVEC + 256)        // 35072

__global__ void __launch_bounds__(K1_THREADS, 1)
k1_gemm(const float* __restrict__ emb, const float* __restrict__ W1,
        const float* __restrict__ b1)
{
    extern __shared__ char smem[];
    const int tid  = threadIdx.x;
    const int lane = tid & 31;
    const int warp = tid >> 5;
    const int m0   = blockIdx.x * K1_MT;

    // ---- B fill: W1c stored [n][k], fp16 ----------------------------------
    // n<64 -> W1[k][n] ; n>=64 -> W1[128+k][n-64]
    for (int idx = tid; idx < 128 * 32; idx += K1_THREADS) {
        const int n = idx >> 5;
        const int c = idx & 31;
        const int k = c * 4;
        const int rs = (n < 64) ? k : (128 + k);
        const int cs = n & 63;
        float vv[4];
        #pragma unroll
        for (int q = 0; q < 4; ++q)
            vv[q] = W1[(size_t)(rs + q) * ATT + cs];
        *reinterpret_cast<uint2*>(smem + SB_OFF + n * ROWB + k * 2) =
            make_uint2(pack_h2(vv[0], vv[1]), pack_h2(vv[2], vv[3]));
    }
    if (tid < 64)
        reinterpret_cast<float*>(smem + SVEC)[tid] = b1[tid];
    __syncthreads();

    // ---- MMA: 16 warps, warp = m16 tile x 16 n8-tiles ---------------------
    float acc[16][4];
    #pragma unroll
    for (int nt = 0; nt < 16; ++nt) {
        acc[nt][0]=0.f; acc[nt][1]=0.f; acc[nt][2]=0.f; acc[nt][3]=0.f;
    }

    const uint32_t bOff = (uint32_t)((lane & 7) * ROWB + (((lane >> 3) & 1) << 4));
    const uint32_t sbB  = cvta_s(smem + SB_OFF);

    // A fragment pointers: rows m0 + warp*16 + (lane>>2) / +8,
    // cols ks*16 + (lane&3)*2 / +8.
    const float* aBase = emb + (size_t)(m0 + warp * 16 + (lane >> 2)) * 128
                       + (lane & 3) * 2;

    // Prefetch ks=0 A fragment
    float2 v0 = *reinterpret_cast<const float2*>(aBase);
    float2 v1 = *reinterpret_cast<const float2*>(aBase + 8 * 128);
    float2 v2 = *reinterpret_cast<const float2*>(aBase + 8);
    float2 v3 = *reinterpret_cast<const float2*>(aBase + 8 * 128 + 8);

    #pragma unroll
    for (int ks = 0; ks < 8; ++ks) {
        // pack current A fragment
        uint32_t a[4];
        a[0] = pack_h2(v0.x, v0.y);
        a[1] = pack_h2(v1.x, v1.y);
        a[2] = pack_h2(v2.x, v2.y);
        a[3] = pack_h2(v3.x, v3.y);
        // prefetch next ks A fragment (overlaps with B LDSM + 16 MMAs)
        if (ks < 7) {
            const float* np = aBase + (ks + 1) * 16;
            v0 = *reinterpret_cast<const float2*>(np);
            v1 = *reinterpret_cast<const float2*>(np + 8 * 128);
            v2 = *reinterpret_cast<const float2*>(np + 8);
            v3 = *reinterpret_cast<const float2*>(np + 8 * 128 + 8);
        }
        // B fragments + MMAs, interleaved for ILP
        #pragma unroll
        for (int nt = 0; nt < 16; ++nt) {
            uint32_t bf[2];
            ldsm_x2(bf, sbB + bOff + ks * 32 + nt * (8 * ROWB));
            mma_f16(acc[nt], a, bf);
        }
    }

    // ---- Epilogue: +b1 (cols 0..63), pack fp16, store half2 words ---------
    const float* b1s = reinterpret_cast<const float*>(smem + SVEC);
    const int r0 = m0 + warp * 16 + (lane >> 2);
    #pragma unroll
    for (int nt = 0; nt < 16; ++nt) {
        const int n = nt * 8 + (lane & 3) * 2;
        float ax = 0.f, ay = 0.f;
        if (n < 64) { ax = b1s[n]; ay = b1s[n + 1]; }
        g_X[(size_t)r0 * 64 + (n >> 1)] =
            pack_h2(acc[nt][0] + ax, acc[nt][1] + ay);
        g_X[(size_t)(r0 + 8) * 64 + (n >> 1)] =
            pack_h2(acc[nt][2] + ax, acc[nt][3] + ay);
    }
}

// ======================= Kernel 2: pairwise relu-dot =======================
// X tile fp16, half2 add+relu, fp32 dot with W2. (R13-R15 proven: 32.8us)
#define K2_THREADS 256
#define K2_BT      4
#define XPH        68                                  // uint32 pitch per row
#define XT_BYTES   (K2_BT * F_SPARSE * XPH * 4)        // 28288
#define SW2_OFF    XT_BYTES
#define SLUT_OFF   (SW2_OFF + 256)
#define K2_SMEM    (SLUT_OFF + 328)                    // 28872

__global__ void __launch_bounds__(K2_THREADS, 6)
k2_pairs(const float* __restrict__ W2, const float* __restrict__ b2,
         float* __restrict__ out)
{
    extern __shared__ char smem[];
    uint32_t* sX = reinterpret_cast<uint32_t*>(smem);
    const int tid   = threadIdx.x;
    const int bbase = blockIdx.x * K2_BT;

    for (int idx = tid; idx < K2_BT * F_SPARSE * 16; idx += K2_THREADS) {
        const int r = idx >> 4;
        const int c = idx & 15;
        const int bl = r / F_SPARSE;
        const int f  = r - bl * F_SPARSE;
        const uint4 v = reinterpret_cast<const uint4*>(
            &g_X[(size_t)(f * BATCH + bbase + bl) * 64])[c];
        *reinterpret_cast<uint4*>(sX + r * XPH + c * 4) = v;
    }
    if (tid < 64)
        reinterpret_cast<float*>(smem + SW2_OFF)[tid] = W2[tid];
    if (tid < F_SPARSE - 1) {
        const int i = tid;
        const int pbase = i * (F_SPARSE - 1) - (i * (i - 1)) / 2;
        const int cnt   = F_SPARSE - 1 - i;
        for (int t = 0; t < cnt; ++t)
            smem[SLUT_OFF + pbase + t] = (char)i;
    }
    const float b2v = b2[0];
    __syncthreads();

    const float4* sW24 = reinterpret_cast<const float4*>(smem + SW2_OFF);
    const __half2 zero2 = __float2half2_rn(0.f);

    for (int idx = tid; idx < K2_BT * NPAIR; idx += K2_THREADS) {
        const int bl = idx / NPAIR;
        const int p  = idx - bl * NPAIR;
        const int i  = (int)smem[SLUT_OFF + p];
        const int pbase = i * (F_SPARSE - 1) - (i * (i - 1)) / 2;
        const int j  = i + 1 + (p - pbase);

        const uint4* Pa = reinterpret_cast<const uint4*>(sX + (bl * F_SPARSE + i) * XPH);
        const uint4* Pb = reinterpret_cast<const uint4*>(sX + (bl * F_SPARSE + j) * XPH + 32);

        float a0 = 0.f, a1 = 0.f;
        #pragma unroll
        for (int t = 0; t < 8; ++t) {
            const uint4 xa = Pa[t];
            const uint4 xb = Pb[t];
            const float4 w0 = sW24[t * 2];
            const float4 w1 = sW24[t * 2 + 1];
            const uint32_t av[4] = {xa.x, xa.y, xa.z, xa.w};
            const uint32_t bv[4] = {xb.x, xb.y, xb.z, xb.w};
            float2 f[4];
            #pragma unroll
            for (int q = 0; q < 4; ++q) {
                const __half2 ha = *reinterpret_cast<const __half2*>(&av[q]);
                const __half2 hb = *reinterpret_cast<const __half2*>(&bv[q]);
                const __half2 s  = __hmax2(__hadd2(ha, hb), zero2);
                f[q] = __half22float2(s);
            }
            a0 = fmaf(f[0].x, w0.x, a0);  a1 = fmaf(f[0].y, w0.y, a1);
            a0 = fmaf(f[1].x, w0.z, a0);  a1 = fmaf(f[1].y, w0.w, a1);
            a0 = fmaf(f[2].x, w1.x, a0);  a1 = fmaf(f[2].y, w1.y, a1);
            a0 = fmaf(f[3].x, w1.z, a0);  a1 = fmaf(f[3].y, w1.w, a1);
        }
        out[(size_t)(bbase + bl) * NPAIR + p] = a0 + a1 + b2v;
    }
}

// =========================== launcher ======================================
extern "C" void kernel_launch(void* const* d_in, const int* in_sizes, int n_in,
                              void* d_out, int out_size) {
    const float* emb = (const float*)d_in[0];
    const float* W1  = (const float*)d_in[1];
    const float* b1  = (const float*)d_in[2];
    const float* W2  = (const float*)d_in[3];
    const float* b2  = (const float*)d_in[4];
    float* out = (float*)d_out;
    (void)in_sizes; (void)n_in; (void)out_size;

    cudaFuncSetAttribute(k1_gemm,
                         cudaFuncAttributeMaxDynamicSharedMemorySize, K1_SMEM);
    cudaFuncSetAttribute(k2_pairs,
                         cudaFuncAttributeMaxDynamicSharedMemorySize, K2_SMEM);

    k1_gemm<<<M_TOTAL / K1_MT, K1_THREADS, K1_SMEM>>>(emb, W1, b1);
    k2_pairs<<<BATCH / K2_BT, K2_THREADS, K2_SMEM>>>(W2, b2, out);
}